// round 12
// baseline (speedup 1.0000x reference)
#include <cuda_runtime.h>
#include <math.h>
#include <stdint.h>

#define Bn 4
#define Sn 512
#define Dn 512
#define Hn 8
#define DKn 64
#define NTAB 33
#define CTXSZ ((size_t)Bn*Sn*Dn)   // 1048576 floats

// Scratch (no allocations allowed -> __device__ globals)
__device__ float g_q[Bn*Hn*Sn*DKn];
__device__ float g_k[Bn*Hn*Sn*DKn];
__device__ float g_vT[Bn*Hn*DKn*Sn];           // V transposed: [b,h,dk,s]
__device__ float g_ctx[4 * (size_t)Bn*Sn*Dn];  // 4 split-K partials (attn*V)
__device__ float g_out[2 * (size_t)Bn*Sn*Dn];  // 2 split-K partials (out-proj)

__device__ __forceinline__ uint32_t to_tf32(float f) {
    uint32_t u;
    asm("cvt.rna.tf32.f32 %0, %1;" : "=r"(u) : "f"(f));
    return u;
}

// convert float4 -> packed tf32 uint4 (single STS.128 at the call site)
__device__ __forceinline__ uint4 tf32x4(float4 v) {
    uint4 w;
    w.x = to_tf32(v.x); w.y = to_tf32(v.y);
    w.z = to_tf32(v.z); w.w = to_tf32(v.w);
    return w;
}

__device__ __forceinline__ void mma_tf32(float* c, const uint32_t* a, const uint32_t* b) {
    asm volatile(
        "mma.sync.aligned.m16n8k8.row.col.f32.tf32.tf32.f32 "
        "{%0,%1,%2,%3}, {%4,%5,%6,%7}, {%8,%9}, {%0,%1,%2,%3};"
        : "+f"(c[0]), "+f"(c[1]), "+f"(c[2]), "+f"(c[3])
        : "r"(a[0]), "r"(a[1]), "r"(a[2]), "r"(a[3]), "r"(b[0]), "r"(b[1]));
}

// ldmatrix x4: 4 8x4-tf32 tiles; thread i supplies row i%8 of tile i/8.
__device__ __forceinline__ void ldsm4(uint32_t* r, const uint32_t* p) {
    uint32_t addr = (uint32_t)__cvta_generic_to_shared(p);
    asm volatile("ldmatrix.sync.aligned.m8n8.x4.shared.b16 {%0,%1,%2,%3}, [%4];"
        : "=r"(r[0]), "=r"(r[1]), "=r"(r[2]), "=r"(r[3]) : "r"(addr));
}

// float4 load; when sum4 set, sums the same offset across the 4 ctx partials.
__device__ __forceinline__ float4 ld_sum4(const float* p, bool sum4) {
    float4 v = *(const float4*)p;
    if (sum4) {
        const float* q = p;
#pragma unroll
        for (int s = 1; s < 4; s++) {
            q += CTXSZ;
            float4 w = *(const float4*)q;
            v.x += w.x; v.y += w.y; v.z += w.z; v.w += w.w;
        }
    }
    return v;
}

// ===========================================================================
// Unified tensor-core tf32 GEMM: D[m,n] = sum_k A[m,k]*B[n,k]
//  mode 0/1/2 (z picks Q/K/V): proj; mode 3: out-proj split-K x2 (z=split,
//    A = sum of 4 ctx partials, writes g_out partial `split`, bias on split 0)
//  mode 4: scores; mode 5: attn*V split-K x4 (z = bh*4+split, K=128/split)
// Template MT = M tile (128 or 64). N tile fixed 64. 256 threads.
// Fragments fed by ldmatrix.x4; smem tile stores are packed STS.128.
// ===========================================================================
template<int MT>
__global__ __launch_bounds__(256) void tc_gemm(
    const float* __restrict__ A0, const float* __restrict__ A1, const float* __restrict__ A2,
    const float* __restrict__ B0, const float* __restrict__ B1, const float* __restrict__ B2,
    const float* __restrict__ bias0, const float* __restrict__ bias1, const float* __restrict__ bias2,
    float* __restrict__ attn, int mode, int kTot)
{
    constexpr int WMc = (MT == 128) ? 4 : 2;
    constexpr int WNc = 8 / WMc;
    constexpr int NFR = 64 / (WNc * 8);          // 128:4, 64:2
    constexpr int AL  = MT / 32;
    constexpr int AWp = MT * 36;
    constexpr int BUFWp = (MT + 64) * 36;

    extern __shared__ uint32_t smem_u[];
    int tid = threadIdx.x;
    int wid = tid >> 5, lane = tid & 31;
    int wm = wid % WMc, wn = wid / WMc;
    int g = lane >> 2, t4 = lane & 3;

    // ldmatrix per-thread row offsets (words)
    int mrow = lane & 7, msel = lane >> 3;
    int a_off = ((msel & 1) * 8 + mrow) * 36 + (msel >> 1) * 4;
    int b_off = ((msel >> 1) * 8 + mrow) * 36 + (msel & 1) * 4;

    int row0 = blockIdx.y * MT;
    int n0   = blockIdx.x * 64;
    int bh   = blockIdx.z;

    const float* Ap; const float* Bp; const float* biasp = nullptr;
    int ldA, ldB, emode, split = 0;
    if (mode == 0) {
        int w = bh;
        Ap = (w == 0) ? A0 : (w == 1) ? A1 : A2;
        Bp = (w == 0) ? B0 : (w == 1) ? B1 : B2;
        biasp = (w == 0) ? bias0 : (w == 1) ? bias1 : bias2;
        ldA = Dn; ldB = Dn; emode = w;
    } else if (mode == 3) {
        split = bh;
        Ap = g_ctx + split * 256;                // K offset into ctx columns
        Bp = B0 + split * 256;
        biasp = bias0; ldA = Dn; ldB = Dn; emode = 3;
    } else if (mode == 4) {
        Ap = g_q + (size_t)bh * Sn * DKn;        // M = queries (i)
        Bp = g_k + (size_t)bh * Sn * DKn;        // N = keys (j)
        ldA = DKn; ldB = DKn; emode = 4;
    } else {
        split = bh & 3; bh >>= 2;
        Ap = attn + (size_t)bh * Sn * Sn + split * 128;
        Bp = g_vT + (size_t)bh * DKn * Sn + split * 128;
        ldA = Sn; ldB = Sn; emode = 5;
    }
    Ap += (size_t)row0 * ldA;
    Bp += (size_t)n0 * ldB;
    const bool sumA = (mode == 3);
    const bool doBias = (mode == 0) || (mode == 3 && split == 0);

    float acc[2][NFR][4];
#pragma unroll
    for (int mi = 0; mi < 2; mi++)
#pragma unroll
        for (int ni = 0; ni < NFR; ni++)
#pragma unroll
            for (int q = 0; q < 4; q++) acc[mi][ni][q] = 0.f;

    float4 pa[AL], pb[2];
    {
        int r = tid >> 3, c4 = tid & 7;
#pragma unroll
        for (int l = 0; l < AL; l++)
            pa[l] = ld_sum4(Ap + (size_t)(r + l * 32) * ldA + c4 * 4, sumA);
#pragma unroll
        for (int l = 0; l < 2; l++)
            pb[l] = *(const float4*)(Bp + (size_t)(r + l * 32) * ldB + c4 * 4);
    }
    {
        int r = tid >> 3, c4 = tid & 7;
        uint32_t* As = smem_u;
        uint32_t* Bs = smem_u + AWp;
#pragma unroll
        for (int l = 0; l < AL; l++)
            *(uint4*)(As + (r + l * 32) * 36 + c4 * 4) = tf32x4(pa[l]);
#pragma unroll
        for (int l = 0; l < 2; l++)
            *(uint4*)(Bs + (r + l * 32) * 36 + c4 * 4) = tf32x4(pb[l]);
    }
    __syncthreads();

    int nk = kTot / 32;
    for (int kc = 0; kc < nk; kc++) {
        if (kc + 1 < nk) {
            int k0 = (kc + 1) * 32;
            int r = tid >> 3, c4 = tid & 7;
#pragma unroll
            for (int l = 0; l < AL; l++)
                pa[l] = ld_sum4(Ap + (size_t)(r + l * 32) * ldA + k0 + c4 * 4, sumA);
#pragma unroll
            for (int l = 0; l < 2; l++)
                pb[l] = *(const float4*)(Bp + (size_t)(r + l * 32) * ldB + k0 + c4 * 4);
        }
        const uint32_t* As = smem_u + (kc & 1) * BUFWp;
        const uint32_t* Bs = As + AWp;
#pragma unroll
        for (int kk = 0; kk < 4; kk++) {
            uint32_t a[2][4], b[NFR][2];
#pragma unroll
            for (int mi = 0; mi < 2; mi++)
                ldsm4(a[mi], As + (wm * 32 + mi * 16) * 36 + a_off + kk * 8);
#pragma unroll
            for (int np = 0; np < NFR / 2; np++) {
                uint32_t rb[4];
                ldsm4(rb, Bs + (wn * (NFR * 8) + np * 16) * 36 + b_off + kk * 8);
                b[np * 2][0] = rb[0]; b[np * 2][1] = rb[1];
                b[np * 2 + 1][0] = rb[2]; b[np * 2 + 1][1] = rb[3];
            }
#pragma unroll
            for (int mi = 0; mi < 2; mi++)
#pragma unroll
                for (int ni = 0; ni < NFR; ni++)
                    mma_tf32(acc[mi][ni], a[mi], b[ni]);
        }
        if (kc + 1 < nk) {
            uint32_t* Aw = smem_u + ((kc + 1) & 1) * BUFWp;
            uint32_t* Bw = Aw + AWp;
            int r = tid >> 3, c4 = tid & 7;
#pragma unroll
            for (int l = 0; l < AL; l++)
                *(uint4*)(Aw + (r + l * 32) * 36 + c4 * 4) = tf32x4(pa[l]);
#pragma unroll
            for (int l = 0; l < 2; l++)
                *(uint4*)(Bw + (r + l * 32) * 36 + c4 * 4) = tf32x4(pb[l]);
            __syncthreads();
        }
    }

#pragma unroll
    for (int mi = 0; mi < 2; mi++) {
        int row = row0 + wm * 32 + mi * 16 + g;
#pragma unroll
        for (int ni = 0; ni < NFR; ni++) {
            int col = n0 + wn * (NFR * 8) + ni * 8 + 2 * t4;
            float v0 = acc[mi][ni][0], v1 = acc[mi][ni][1];
            float v2 = acc[mi][ni][2], v3 = acc[mi][ni][3];
            if (doBias) {
                float b0v = biasp[col], b1v = biasp[col + 1];
                v0 += b0v; v1 += b1v; v2 += b0v; v3 += b1v;
            }
            if (emode <= 2) {
                int b = row >> 9, s = row & 511;
                int h = col >> 6, dk = col & 63;
                if (emode == 0) {
                    float* p = g_q + (((size_t)(b * Hn + h)) * Sn + s) * DKn + dk;
                    *(float2*)p = make_float2(v0, v1);
                    *(float2*)(p + 8 * DKn) = make_float2(v2, v3);
                } else if (emode == 1) {
                    float* p = g_k + (((size_t)(b * Hn + h)) * Sn + s) * DKn + dk;
                    *(float2*)p = make_float2(v0, v1);
                    *(float2*)(p + 8 * DKn) = make_float2(v2, v3);
                } else {
                    float* p = g_vT + (((size_t)(b * Hn + h)) * DKn + dk) * Sn + s;
                    p[0] = v0; p[Sn] = v1; p[8] = v2; p[Sn + 8] = v3;
                }
            } else if (emode == 3) {
                float* p = g_out + (size_t)split * CTXSZ + (size_t)row * Dn + col;
                *(float2*)p = make_float2(v0, v1);
                *(float2*)(p + 8 * Dn) = make_float2(v2, v3);
            } else if (emode == 4) {
                float* p = attn + ((size_t)bh * Sn + row) * Sn + col;
                *(float2*)p = make_float2(v0 * 0.125f, v1 * 0.125f);
                *(float2*)(p + 8 * Sn) = make_float2(v2 * 0.125f, v3 * 0.125f);
            } else {
                int b = bh >> 3, h = bh & 7;
                float* p = g_ctx + (size_t)split * CTXSZ
                         + ((size_t)b * Sn + row) * Dn + h * DKn + col;
                *(float2*)p = make_float2(v0, v1);
                *(float2*)(p + 8 * Dn) = make_float2(v2, v3);
            }
        }
    }
}

// ===========================================================================
// Fused relative-position bias + mask + softmax, bias dot via mma.sync tf32.
// Bias results held in registers through the tile loop; s_row aliases vbuf's
// storage afterwards (saves 16KB smem -> higher occupancy).
// ===========================================================================
__global__ __launch_bounds__(256) void bias_softmax_kernel(
    const int* __restrict__ rp, const float* __restrict__ rel_table,
    const int* __restrict__ mask, float* __restrict__ attn)
{
    __shared__ __align__(16) uint32_t qs_p[8 * 68];
    __shared__ __align__(16) uint32_t pool[2 * 64 * 68];   // vbuf, later s_row
    __shared__ float tms[NTAB + 3];
    __shared__ int mask_s[Sn];

    uint32_t* vbuf0 = pool;
    uint32_t* vbuf1 = pool + 64 * 68;
    float* s_row = (float*)pool;                 // aliased after tile loop

    int i = blockIdx.x;
    int b = blockIdx.y;
    int tid = threadIdx.x;
    int wid = tid >> 5, lane = tid & 31;
    int g = lane >> 2, t4 = lane & 3;
    int half = wid >> 2;
    int jq = wid & 3;

    if (tid < NTAB) {
        float s = 0.f;
#pragma unroll
        for (int e = 0; e < DKn; e++) s += rel_table[tid * DKn + e];
        tms[tid] = __uint_as_float(to_tf32(s * (1.0f / DKn)));
    }
    for (int l = tid; l < Hn * DKn; l += 256) {
        int h = l >> 6, d = l & 63;
        qs_p[h * 68 + d] = to_tf32(g_q[(((size_t)b * Hn + h) * Sn + i) * DKn + d]);
    }
    {
        mask_s[tid] = mask[b * Sn + tid];
        mask_s[tid + 256] = mask[b * Sn + tid + 256];
    }

    const int4* src = (const int4*)(rp + (((size_t)b * Sn + i) * Sn) * DKn);

    int4 pre[8];
#pragma unroll
    for (int l = 0; l < 8; l++) pre[l] = src[tid + l * 256];
    __syncthreads();

    float cb[4][4];                              // bias results, all 4 iterations
    for (int jt2 = 0; jt2 < 4; jt2++) {
#pragma unroll
        for (int l = 0; l < 8; l++) {
            uint32_t* vb = (l < 4) ? vbuf0 : vbuf1;
            int q4 = tid + (l & 3) * 256;
            int4 v = pre[l];
            int e = q4 * 4;
            int j = e >> 6, d = e & 63;
            float4 f;
            f.x = tms[min(max(v.x, -16), 16) + 16];
            f.y = tms[min(max(v.y, -16), 16) + 16];
            f.z = tms[min(max(v.z, -16), 16) + 16];
            f.w = tms[min(max(v.w, -16), 16) + 16];
            *(float4*)&vb[j * 68 + d] = f;
        }
        __syncthreads();
        if (jt2 + 1 < 4) {
#pragma unroll
            for (int l = 0; l < 8; l++)
                pre[l] = src[(size_t)(jt2 + 1) * 2048 + tid + l * 256];
        }
        const uint32_t* Vb = half ? vbuf1 : vbuf0;
        float c[4] = {0.f, 0.f, 0.f, 0.f};
#pragma unroll
        for (int kk = 0; kk < 8; kk++) {
            int kb = kk * 8 + t4;
            uint32_t a[4], bb[2];
            int r = (jq * 16 + g) * 68 + kb;
            a[0] = Vb[r];
            a[1] = Vb[r + 8 * 68];
            a[2] = Vb[r + 4];
            a[3] = Vb[r + 8 * 68 + 4];
            bb[0] = qs_p[g * 68 + kb];
            bb[1] = qs_p[g * 68 + kb + 4];
            mma_tf32(c, a, bb);
        }
#pragma unroll
        for (int q = 0; q < 4; q++) cb[jt2][q] = c[q];
        __syncthreads();
    }

    // vbuf dead; write register-held bias into s_row (aliased storage)
#pragma unroll
    for (int jt2 = 0; jt2 < 4; jt2++) {
        int jbase = (jt2 * 2 + half) * 64 + jq * 16;
        s_row[(2 * t4) * Sn + jbase + g] = cb[jt2][0];
        s_row[(2 * t4 + 1) * Sn + jbase + g] = cb[jt2][1];
        s_row[(2 * t4) * Sn + jbase + g + 8] = cb[jt2][2];
        s_row[(2 * t4 + 1) * Sn + jbase + g + 8] = cb[jt2][3];
    }
    __syncthreads();

    float* grow = attn + (((size_t)(b * Hn + wid)) * Sn + i) * Sn;
    float v[16];
    float mx = -3.0e38f;
#pragma unroll
    for (int k = 0; k < 16; k++) {
        int j = lane + k * 32;
        float x = grow[j] + s_row[wid * Sn + j];
        if (mask_s[j] == 0) x = -1e9f;
        v[k] = x;
        mx = fmaxf(mx, x);
    }
#pragma unroll
    for (int off = 16; off; off >>= 1) mx = fmaxf(mx, __shfl_xor_sync(0xffffffffu, mx, off));
    float s = 0.f;
#pragma unroll
    for (int k = 0; k < 16; k++) { v[k] = __expf(v[k] - mx); s += v[k]; }
#pragma unroll
    for (int off = 16; off; off >>= 1) s += __shfl_xor_sync(0xffffffffu, s, off);
    float inv = 1.0f / s;
#pragma unroll
    for (int k = 0; k < 16; k++) grow[lane + k * 32] = v[k] * inv;
}

// ---------------------------------------------------------------------------
// y = LayerNorm(out0 + out1 + query) * gamma + beta
// ---------------------------------------------------------------------------
__global__ __launch_bounds__(256) void ln_kernel(const float* __restrict__ query,
                                                 const float* __restrict__ gamma,
                                                 const float* __restrict__ beta,
                                                 float* __restrict__ y)
{
    int row = blockIdx.x;
    int tid = threadIdx.x;
    size_t base = (size_t)row * Dn;
    float x0 = g_out[base + tid] + g_out[CTXSZ + base + tid] + query[base + tid];
    float x1 = g_out[base + tid + 256] + g_out[CTXSZ + base + tid + 256] + query[base + tid + 256];
    float s = x0 + x1, sq = x0 * x0 + x1 * x1;
    __shared__ float r1[8], r2[8];
#pragma unroll
    for (int off = 16; off; off >>= 1) {
        s += __shfl_xor_sync(0xffffffffu, s, off);
        sq += __shfl_xor_sync(0xffffffffu, sq, off);
    }
    if ((tid & 31) == 0) { r1[tid >> 5] = s; r2[tid >> 5] = sq; }
    __syncthreads();
    s = 0.f; sq = 0.f;
#pragma unroll
    for (int w = 0; w < 8; w++) { s += r1[w]; sq += r2[w]; }
    float mean = s * (1.0f / Dn);
    float var = sq * (1.0f / Dn) - mean * mean;
    float rstd = rsqrtf(var + 1e-5f);
    y[base + tid]       = (x0 - mean) * rstd * gamma[tid] + beta[tid];
    y[base + tid + 256] = (x1 - mean) * rstd * gamma[tid + 256] + beta[tid + 256];
}

// ---------------------------------------------------------------------------
extern "C" void kernel_launch(void* const* d_in, const int* in_sizes, int n_in,
                              void* d_out, int out_size)
{
    (void)in_sizes; (void)n_in; (void)out_size;
    const float* query = (const float*)d_in[0];
    const float* key   = (const float*)d_in[1];
    const float* value = (const float*)d_in[2];
    const float* Wq = (const float*)d_in[3];
    const float* bq = (const float*)d_in[4];
    const float* Wk = (const float*)d_in[5];
    const float* bk = (const float*)d_in[6];
    const float* Wv = (const float*)d_in[7];
    const float* bv = (const float*)d_in[8];
    const float* Wo = (const float*)d_in[9];
    const float* bo = (const float*)d_in[10];
    const float* rel_table = (const float*)d_in[11];
    const float* gamma = (const float*)d_in[12];
    const float* beta  = (const float*)d_in[13];
    const int* mask = (const int*)d_in[14];
    const int* rp   = (const int*)d_in[15];

    float* y = (float*)d_out;                        // [B,S,D]
    float* attn = y + (size_t)Bn * Sn * Dn;          // [B,H,S,S]

    const int SMB128 = 2 * (128 + 64) * 36 * 4;      // 55296
    const int SMB64  = 2 * (64 + 64) * 36 * 4;       // 36864
    cudaFuncSetAttribute(tc_gemm<128>, cudaFuncAttributeMaxDynamicSharedMemorySize, SMB128);
    cudaFuncSetAttribute(tc_gemm<64>,  cudaFuncAttributeMaxDynamicSharedMemorySize, SMB64);

    // fused QKV projections (MT=128, 384 CTAs)
    tc_gemm<128><<<dim3(8, 16, 3), 256, SMB128>>>(query, key, value, Wq, Wk, Wv,
                                                  bq, bk, bv, nullptr, 0, 512);
    // scores
    tc_gemm<128><<<dim3(8, 4, 32), 256, SMB128>>>(nullptr, nullptr, nullptr, nullptr, nullptr, nullptr,
                                                  nullptr, nullptr, nullptr, attn, 4, 64);
    // fused rel-pos bias + mask + softmax (bias via mma, smem-reduced)
    bias_softmax_kernel<<<dim3(Sn, Bn), 256>>>(rp, rel_table, mask, attn);
    // attn @ V  split-K x4 -> 1024 CTAs, each K=128, writes partial ctx buffer
    tc_gemm<64><<<dim3(1, 8, 128), 256, SMB64>>>(nullptr, nullptr, nullptr, nullptr, nullptr, nullptr,
                                                 nullptr, nullptr, nullptr, attn, 5, 128);
    // out projection split-K x2 (A = sum of 4 ctx partials during load)
    tc_gemm<64><<<dim3(8, 32, 2), 256, SMB64>>>(nullptr, nullptr, nullptr, Wo, nullptr, nullptr,
                                                bo, nullptr, nullptr, nullptr, 3, 256);
    ln_kernel<<<Bn * Sn, 256>>>(query, gamma, beta, y);
}

// round 14
// speedup vs baseline: 1.4813x; 1.4813x over previous
#include <cuda_runtime.h>
#include <math.h>
#include <stdint.h>

#define Bn 4
#define Sn 512
#define Dn 512
#define Hn 8
#define DKn 64
#define NTAB 33
#define CTXSZ ((size_t)Bn*Sn*Dn)   // 1048576 floats

// Scratch (no allocations allowed -> __device__ globals)
__device__ float g_q[Bn*Hn*Sn*DKn];
__device__ float g_k[Bn*Hn*Sn*DKn];
__device__ float g_vT[Bn*Hn*DKn*Sn];           // V transposed: [b,h,dk,s]
__device__ float g_ctx[4 * (size_t)Bn*Sn*Dn];  // 4 split-K partials (attn*V)
__device__ float g_out[2 * (size_t)Bn*Sn*Dn];  // 2 split-K partials (out-proj)

__device__ __forceinline__ uint32_t to_tf32(float f) {
    uint32_t u;
    asm("cvt.rna.tf32.f32 %0, %1;" : "=r"(u) : "f"(f));
    return u;
}
__device__ __forceinline__ uint32_t cvt_bits(uint32_t x) {
    uint32_t u;
    asm("cvt.rna.tf32.f32 %0, %1;" : "=r"(u) : "f"(__uint_as_float(x)));
    return u;
}

__device__ __forceinline__ void mma_tf32(float* c, const uint32_t* a, const uint32_t* b) {
    asm volatile(
        "mma.sync.aligned.m16n8k8.row.col.f32.tf32.tf32.f32 "
        "{%0,%1,%2,%3}, {%4,%5,%6,%7}, {%8,%9}, {%0,%1,%2,%3};"
        : "+f"(c[0]), "+f"(c[1]), "+f"(c[2]), "+f"(c[3])
        : "r"(a[0]), "r"(a[1]), "r"(a[2]), "r"(a[3]), "r"(b[0]), "r"(b[1]));
}

// ldmatrix x4: 4 8x4-tf32 tiles; thread i supplies row i%8 of tile i/8.
__device__ __forceinline__ void ldsm4(uint32_t* r, const uint32_t* p) {
    uint32_t addr = (uint32_t)__cvta_generic_to_shared(p);
    asm volatile("ldmatrix.sync.aligned.m8n8.x4.shared.b16 {%0,%1,%2,%3}, [%4];"
        : "=r"(r[0]), "=r"(r[1]), "=r"(r[2]), "=r"(r[3]) : "r"(addr));
}

// 16B async copy gmem -> smem
__device__ __forceinline__ void cp16(uint32_t smem_addr, const void* g) {
    asm volatile("cp.async.cg.shared.global [%0], [%1], 16;"
                 :: "r"(smem_addr), "l"(g) : "memory");
}

// float4 load summing the same offset across the 4 ctx partials.
__device__ __forceinline__ float4 ld_sum4(const float* p) {
    float4 v = *(const float4*)p;
    const float* q = p;
#pragma unroll
    for (int s = 1; s < 4; s++) {
        q += CTXSZ;
        float4 w = *(const float4*)q;
        v.x += w.x; v.y += w.y; v.z += w.z; v.w += w.w;
    }
    return v;
}

// ===========================================================================
// Unified tensor-core tf32 GEMM: D[m,n] = sum_k A[m,k]*B[n,k]
//  mode 0/1/2 (z picks Q/K/V): proj; mode 3: out-proj split-K x2 (z=split,
//    A = sum of 4 ctx partials, writes g_out partial `split`, bias on split 0)
//  mode 4: scores; mode 5: attn*V split-K x4 (z = bh*4+split, K=128/split)
// Template MT = M tile (128 or 64). N tile fixed 64. 256 threads.
// Tiles land raw fp32 in smem via cp.async (3 buffers, depth-2, 1 sync/chunk);
// tf32 conversion happens on fragment registers after ldmatrix.
// ===========================================================================
template<int MT>
__global__ __launch_bounds__(256) void tc_gemm(
    const float* __restrict__ A0, const float* __restrict__ A1, const float* __restrict__ A2,
    const float* __restrict__ B0, const float* __restrict__ B1, const float* __restrict__ B2,
    const float* __restrict__ bias0, const float* __restrict__ bias1, const float* __restrict__ bias2,
    float* __restrict__ attn, int mode, int kTot)
{
    constexpr int WMc = (MT == 128) ? 4 : 2;
    constexpr int WNc = 8 / WMc;
    constexpr int NFR = 64 / (WNc * 8);          // 128:4, 64:2
    constexpr int AL  = MT / 32;
    constexpr int AWp = MT * 36;
    constexpr int BUFWp = (MT + 64) * 36;

    extern __shared__ uint32_t smem_u[];
    int tid = threadIdx.x;
    int wid = tid >> 5, lane = tid & 31;
    int wm = wid % WMc, wn = wid / WMc;
    int g = lane >> 2, t4 = lane & 3;

    // ldmatrix per-thread row offsets (words)
    int mrow = lane & 7, msel = lane >> 3;
    int a_off = ((msel & 1) * 8 + mrow) * 36 + (msel >> 1) * 4;
    int b_off = ((msel >> 1) * 8 + mrow) * 36 + (msel & 1) * 4;

    int row0 = blockIdx.y * MT;
    int n0   = blockIdx.x * 64;
    int bh   = blockIdx.z;

    const float* Ap; const float* Bp; const float* biasp = nullptr;
    int ldA, ldB, emode, split = 0;
    if (mode == 0) {
        int w = bh;
        Ap = (w == 0) ? A0 : (w == 1) ? A1 : A2;
        Bp = (w == 0) ? B0 : (w == 1) ? B1 : B2;
        biasp = (w == 0) ? bias0 : (w == 1) ? bias1 : bias2;
        ldA = Dn; ldB = Dn; emode = w;
    } else if (mode == 3) {
        split = bh;
        Ap = g_ctx + split * 256;                // K offset into ctx columns
        Bp = B0 + split * 256;
        biasp = bias0; ldA = Dn; ldB = Dn; emode = 3;
    } else if (mode == 4) {
        Ap = g_q + (size_t)bh * Sn * DKn;        // M = queries (i)
        Bp = g_k + (size_t)bh * Sn * DKn;        // N = keys (j)
        ldA = DKn; ldB = DKn; emode = 4;
    } else {
        split = bh & 3; bh >>= 2;
        Ap = attn + (size_t)bh * Sn * Sn + split * 128;
        Bp = g_vT + (size_t)bh * DKn * Sn + split * 128;
        ldA = Sn; ldB = Sn; emode = 5;
    }
    Ap += (size_t)row0 * ldA;
    Bp += (size_t)n0 * ldB;
    const bool sumA = (mode == 3);
    const bool doBias = (mode == 0) || (mode == 3 && split == 0);

    uint32_t smem_addr0 = (uint32_t)__cvta_generic_to_shared(smem_u);
    int rr = tid >> 3, c4 = tid & 7;

    // issue one 32-k chunk c into buffer b (one commit group per call)
    auto issue_chunk = [&](int c, int b) {
        int k0 = c * 32;
        uint32_t Ab = smem_addr0 + (uint32_t)(b * BUFWp) * 4u;
        uint32_t Bb = Ab + (uint32_t)AWp * 4u;
        if (sumA) {
            float* As = (float*)(smem_u + b * BUFWp);
#pragma unroll
            for (int l = 0; l < AL; l++) {
                float4 v = ld_sum4(Ap + (size_t)(rr + l * 32) * ldA + k0 + c4 * 4);
                float* d = As + (rr + l * 32) * 36 + c4 * 4;
                d[0] = v.x; d[1] = v.y; d[2] = v.z; d[3] = v.w;
            }
        } else {
#pragma unroll
            for (int l = 0; l < AL; l++)
                cp16(Ab + (uint32_t)((rr + l * 32) * 36 + c4 * 4) * 4u,
                     Ap + (size_t)(rr + l * 32) * ldA + k0 + c4 * 4);
        }
#pragma unroll
        for (int l = 0; l < 2; l++)
            cp16(Bb + (uint32_t)((rr + l * 32) * 36 + c4 * 4) * 4u,
                 Bp + (size_t)(rr + l * 32) * ldB + k0 + c4 * 4);
        asm volatile("cp.async.commit_group;" ::: "memory");
    };

    float acc[2][NFR][4];
#pragma unroll
    for (int mi = 0; mi < 2; mi++)
#pragma unroll
        for (int ni = 0; ni < NFR; ni++)
#pragma unroll
            for (int q = 0; q < 4; q++) acc[mi][ni][q] = 0.f;

    int nk = kTot / 32;
    issue_chunk(0, 0);
    if (nk > 1) issue_chunk(1, 1);

    for (int kc = 0; kc < nk; kc++) {
        if (kc + 1 < nk) asm volatile("cp.async.wait_group 1;" ::: "memory");
        else             asm volatile("cp.async.wait_group 0;" ::: "memory");
        __syncthreads();
        // safe: buffer (kc+2)%3 was last read at iteration kc-1, and every
        // warp passed this iteration's barrier after finishing that MMA.
        if (kc + 2 < nk) issue_chunk(kc + 2, (kc + 2) % 3);

        const uint32_t* As = smem_u + (kc % 3) * BUFWp;
        const uint32_t* Bs = As + AWp;
#pragma unroll
        for (int kk = 0; kk < 4; kk++) {
            uint32_t a[2][4], b[NFR][2];
#pragma unroll
            for (int mi = 0; mi < 2; mi++)
                ldsm4(a[mi], As + (wm * 32 + mi * 16) * 36 + a_off + kk * 8);
#pragma unroll
            for (int np = 0; np < NFR / 2; np++) {
                uint32_t rb[4];
                ldsm4(rb, Bs + (wn * (NFR * 8) + np * 16) * 36 + b_off + kk * 8);
                b[np * 2][0] = rb[0]; b[np * 2][1] = rb[1];
                b[np * 2 + 1][0] = rb[2]; b[np * 2 + 1][1] = rb[3];
            }
            // raw fp32 -> tf32 on fragments (same cvt.rna as before)
#pragma unroll
            for (int mi = 0; mi < 2; mi++)
#pragma unroll
                for (int t = 0; t < 4; t++) a[mi][t] = cvt_bits(a[mi][t]);
#pragma unroll
            for (int ni = 0; ni < NFR; ni++) {
                b[ni][0] = cvt_bits(b[ni][0]);
                b[ni][1] = cvt_bits(b[ni][1]);
            }
#pragma unroll
            for (int mi = 0; mi < 2; mi++)
#pragma unroll
                for (int ni = 0; ni < NFR; ni++)
                    mma_tf32(acc[mi][ni], a[mi], b[ni]);
        }
    }

#pragma unroll
    for (int mi = 0; mi < 2; mi++) {
        int row = row0 + wm * 32 + mi * 16 + g;
#pragma unroll
        for (int ni = 0; ni < NFR; ni++) {
            int col = n0 + wn * (NFR * 8) + ni * 8 + 2 * t4;
            float v0 = acc[mi][ni][0], v1 = acc[mi][ni][1];
            float v2 = acc[mi][ni][2], v3 = acc[mi][ni][3];
            if (doBias) {
                float b0v = biasp[col], b1v = biasp[col + 1];
                v0 += b0v; v1 += b1v; v2 += b0v; v3 += b1v;
            }
            if (emode <= 2) {
                int b = row >> 9, s = row & 511;
                int h = col >> 6, dk = col & 63;
                if (emode == 0) {
                    float* p = g_q + (((size_t)(b * Hn + h)) * Sn + s) * DKn + dk;
                    *(float2*)p = make_float2(v0, v1);
                    *(float2*)(p + 8 * DKn) = make_float2(v2, v3);
                } else if (emode == 1) {
                    float* p = g_k + (((size_t)(b * Hn + h)) * Sn + s) * DKn + dk;
                    *(float2*)p = make_float2(v0, v1);
                    *(float2*)(p + 8 * DKn) = make_float2(v2, v3);
                } else {
                    float* p = g_vT + (((size_t)(b * Hn + h)) * DKn + dk) * Sn + s;
                    p[0] = v0; p[Sn] = v1; p[8] = v2; p[Sn + 8] = v3;
                }
            } else if (emode == 3) {
                float* p = g_out + (size_t)split * CTXSZ + (size_t)row * Dn + col;
                *(float2*)p = make_float2(v0, v1);
                *(float2*)(p + 8 * Dn) = make_float2(v2, v3);
            } else if (emode == 4) {
                float* p = attn + ((size_t)bh * Sn + row) * Sn + col;
                *(float2*)p = make_float2(v0 * 0.125f, v1 * 0.125f);
                *(float2*)(p + 8 * Sn) = make_float2(v2 * 0.125f, v3 * 0.125f);
            } else {
                int b = bh >> 3, h = bh & 7;
                float* p = g_ctx + (size_t)split * CTXSZ
                         + ((size_t)b * Sn + row) * Dn + h * DKn + col;
                *(float2*)p = make_float2(v0, v1);
                *(float2*)(p + 8 * Dn) = make_float2(v2, v3);
            }
        }
    }
}

// ===========================================================================
// Fused relative-position bias + mask + softmax (unchanged from R11).
// ===========================================================================
__global__ __launch_bounds__(256) void bias_softmax_kernel(
    const int* __restrict__ rp, const float* __restrict__ rel_table,
    const int* __restrict__ mask, float* __restrict__ attn)
{
    __shared__ __align__(16) uint32_t qs_p[8 * 68];
    __shared__ __align__(16) uint32_t pool[2 * 64 * 68];   // vbuf, later s_row
    __shared__ float tms[NTAB + 3];
    __shared__ int mask_s[Sn];

    uint32_t* vbuf0 = pool;
    uint32_t* vbuf1 = pool + 64 * 68;
    float* s_row = (float*)pool;                 // aliased after tile loop

    int i = blockIdx.x;
    int b = blockIdx.y;
    int tid = threadIdx.x;
    int wid = tid >> 5, lane = tid & 31;
    int g = lane >> 2, t4 = lane & 3;
    int half = wid >> 2;
    int jq = wid & 3;

    if (tid < NTAB) {
        float s = 0.f;
#pragma unroll
        for (int e = 0; e < DKn; e++) s += rel_table[tid * DKn + e];
        tms[tid] = __uint_as_float(to_tf32(s * (1.0f / DKn)));
    }
    for (int l = tid; l < Hn * DKn; l += 256) {
        int h = l >> 6, d = l & 63;
        qs_p[h * 68 + d] = to_tf32(g_q[(((size_t)b * Hn + h) * Sn + i) * DKn + d]);
    }
    {
        mask_s[tid] = mask[b * Sn + tid];
        mask_s[tid + 256] = mask[b * Sn + tid + 256];
    }

    const int4* src = (const int4*)(rp + (((size_t)b * Sn + i) * Sn) * DKn);

    int4 pre[8];
#pragma unroll
    for (int l = 0; l < 8; l++) pre[l] = src[tid + l * 256];
    __syncthreads();

    float cb[4][4];                              // bias results, all 4 iterations
    for (int jt2 = 0; jt2 < 4; jt2++) {
#pragma unroll
        for (int l = 0; l < 8; l++) {
            uint32_t* vb = (l < 4) ? vbuf0 : vbuf1;
            int q4 = tid + (l & 3) * 256;
            int4 v = pre[l];
            int e = q4 * 4;
            int j = e >> 6, d = e & 63;
            float4 f;
            f.x = tms[min(max(v.x, -16), 16) + 16];
            f.y = tms[min(max(v.y, -16), 16) + 16];
            f.z = tms[min(max(v.z, -16), 16) + 16];
            f.w = tms[min(max(v.w, -16), 16) + 16];
            *(float4*)&vb[j * 68 + d] = f;
        }
        __syncthreads();
        if (jt2 + 1 < 4) {
#pragma unroll
            for (int l = 0; l < 8; l++)
                pre[l] = src[(size_t)(jt2 + 1) * 2048 + tid + l * 256];
        }
        const uint32_t* Vb = half ? vbuf1 : vbuf0;
        float c[4] = {0.f, 0.f, 0.f, 0.f};
#pragma unroll
        for (int kk = 0; kk < 8; kk++) {
            int kb = kk * 8 + t4;
            uint32_t a[4], bb[2];
            int r = (jq * 16 + g) * 68 + kb;
            a[0] = Vb[r];
            a[1] = Vb[r + 8 * 68];
            a[2] = Vb[r + 4];
            a[3] = Vb[r + 8 * 68 + 4];
            bb[0] = qs_p[g * 68 + kb];
            bb[1] = qs_p[g * 68 + kb + 4];
            mma_tf32(c, a, bb);
        }
#pragma unroll
        for (int q = 0; q < 4; q++) cb[jt2][q] = c[q];
        __syncthreads();
    }

    // vbuf dead; write register-held bias into s_row (aliased storage)
#pragma unroll
    for (int jt2 = 0; jt2 < 4; jt2++) {
        int jbase = (jt2 * 2 + half) * 64 + jq * 16;
        s_row[(2 * t4) * Sn + jbase + g] = cb[jt2][0];
        s_row[(2 * t4 + 1) * Sn + jbase + g] = cb[jt2][1];
        s_row[(2 * t4) * Sn + jbase + g + 8] = cb[jt2][2];
        s_row[(2 * t4 + 1) * Sn + jbase + g + 8] = cb[jt2][3];
    }
    __syncthreads();

    float* grow = attn + (((size_t)(b * Hn + wid)) * Sn + i) * Sn;
    float v[16];
    float mx = -3.0e38f;
#pragma unroll
    for (int k = 0; k < 16; k++) {
        int j = lane + k * 32;
        float x = grow[j] + s_row[wid * Sn + j];
        if (mask_s[j] == 0) x = -1e9f;
        v[k] = x;
        mx = fmaxf(mx, x);
    }
#pragma unroll
    for (int off = 16; off; off >>= 1) mx = fmaxf(mx, __shfl_xor_sync(0xffffffffu, mx, off));
    float s = 0.f;
#pragma unroll
    for (int k = 0; k < 16; k++) { v[k] = __expf(v[k] - mx); s += v[k]; }
#pragma unroll
    for (int off = 16; off; off >>= 1) s += __shfl_xor_sync(0xffffffffu, s, off);
    float inv = 1.0f / s;
#pragma unroll
    for (int k = 0; k < 16; k++) grow[lane + k * 32] = v[k] * inv;
}

// ---------------------------------------------------------------------------
// y = LayerNorm(out0 + out1 + query) * gamma + beta
// ---------------------------------------------------------------------------
__global__ __launch_bounds__(256) void ln_kernel(const float* __restrict__ query,
                                                 const float* __restrict__ gamma,
                                                 const float* __restrict__ beta,
                                                 float* __restrict__ y)
{
    int row = blockIdx.x;
    int tid = threadIdx.x;
    size_t base = (size_t)row * Dn;
    float x0 = g_out[base + tid] + g_out[CTXSZ + base + tid] + query[base + tid];
    float x1 = g_out[base + tid + 256] + g_out[CTXSZ + base + tid + 256] + query[base + tid + 256];
    float s = x0 + x1, sq = x0 * x0 + x1 * x1;
    __shared__ float r1[8], r2[8];
#pragma unroll
    for (int off = 16; off; off >>= 1) {
        s += __shfl_xor_sync(0xffffffffu, s, off);
        sq += __shfl_xor_sync(0xffffffffu, sq, off);
    }
    if ((tid & 31) == 0) { r1[tid >> 5] = s; r2[tid >> 5] = sq; }
    __syncthreads();
    s = 0.f; sq = 0.f;
#pragma unroll
    for (int w = 0; w < 8; w++) { s += r1[w]; sq += r2[w]; }
    float mean = s * (1.0f / Dn);
    float var = sq * (1.0f / Dn) - mean * mean;
    float rstd = rsqrtf(var + 1e-5f);
    y[base + tid]       = (x0 - mean) * rstd * gamma[tid] + beta[tid];
    y[base + tid + 256] = (x1 - mean) * rstd * gamma[tid + 256] + beta[tid + 256];
}

// ---------------------------------------------------------------------------
extern "C" void kernel_launch(void* const* d_in, const int* in_sizes, int n_in,
                              void* d_out, int out_size)
{
    (void)in_sizes; (void)n_in; (void)out_size;
    const float* query = (const float*)d_in[0];
    const float* key   = (const float*)d_in[1];
    const float* value = (const float*)d_in[2];
    const float* Wq = (const float*)d_in[3];
    const float* bq = (const float*)d_in[4];
    const float* Wk = (const float*)d_in[5];
    const float* bk = (const float*)d_in[6];
    const float* Wv = (const float*)d_in[7];
    const float* bv = (const float*)d_in[8];
    const float* Wo = (const float*)d_in[9];
    const float* bo = (const float*)d_in[10];
    const float* rel_table = (const float*)d_in[11];
    const float* gamma = (const float*)d_in[12];
    const float* beta  = (const float*)d_in[13];
    const int* mask = (const int*)d_in[14];
    const int* rp   = (const int*)d_in[15];

    float* y = (float*)d_out;                        // [B,S,D]
    float* attn = y + (size_t)Bn * Sn * Dn;          // [B,H,S,S]

    const int SMB128 = 3 * (128 + 64) * 36 * 4;      // 82944
    const int SMB64  = 3 * (64 + 64) * 36 * 4;       // 55296
    cudaFuncSetAttribute(tc_gemm<128>, cudaFuncAttributeMaxDynamicSharedMemorySize, SMB128);
    cudaFuncSetAttribute(tc_gemm<64>,  cudaFuncAttributeMaxDynamicSharedMemorySize, SMB64);

    // fused QKV projections (MT=128, 384 CTAs)
    tc_gemm<128><<<dim3(8, 16, 3), 256, SMB128>>>(query, key, value, Wq, Wk, Wv,
                                                  bq, bk, bv, nullptr, 0, 512);
    // scores
    tc_gemm<128><<<dim3(8, 4, 32), 256, SMB128>>>(nullptr, nullptr, nullptr, nullptr, nullptr, nullptr,
                                                  nullptr, nullptr, nullptr, attn, 4, 64);
    // fused rel-pos bias + mask + softmax (bias via mma, smem-reduced)
    bias_softmax_kernel<<<dim3(Sn, Bn), 256>>>(rp, rel_table, mask, attn);
    // attn @ V  split-K x4 -> 1024 CTAs, each K=128, writes partial ctx buffer
    tc_gemm<64><<<dim3(1, 8, 128), 256, SMB64>>>(nullptr, nullptr, nullptr, nullptr, nullptr, nullptr,
                                                 nullptr, nullptr, nullptr, attn, 5, 128);
    // out projection split-K x2 (A = sum of 4 ctx partials during load)
    tc_gemm<64><<<dim3(8, 32, 2), 256, SMB64>>>(nullptr, nullptr, nullptr, Wo, nullptr, nullptr,
                                                bo, nullptr, nullptr, nullptr, 3, 256);
    ln_kernel<<<Bn * Sn, 256>>>(query, gamma, beta, y);
}

// round 15
// speedup vs baseline: 1.5581x; 1.0519x over previous
#include <cuda_runtime.h>
#include <math.h>
#include <stdint.h>

#define Bn 4
#define Sn 512
#define Dn 512
#define Hn 8
#define DKn 64
#define NTAB 33
#define CTXSZ ((size_t)Bn*Sn*Dn)   // 1048576 floats

// Scratch (no allocations allowed -> __device__ globals)
__device__ float g_q[Bn*Hn*Sn*DKn];
__device__ float g_k[Bn*Hn*Sn*DKn];
__device__ float g_vT[Bn*Hn*DKn*Sn];           // V transposed: [b,h,dk,s]
__device__ float g_ctx[4 * (size_t)Bn*Sn*Dn];  // 4 split-K partials (attn*V)
__device__ float g_out[2 * (size_t)Bn*Sn*Dn];  // 2 split-K partials (out-proj)

__device__ __forceinline__ uint32_t to_tf32(float f) {
    uint32_t u;
    asm("cvt.rna.tf32.f32 %0, %1;" : "=r"(u) : "f"(f));
    return u;
}

__device__ __forceinline__ void mma_tf32(float* c, const uint32_t* a, const uint32_t* b) {
    asm volatile(
        "mma.sync.aligned.m16n8k8.row.col.f32.tf32.tf32.f32 "
        "{%0,%1,%2,%3}, {%4,%5,%6,%7}, {%8,%9}, {%0,%1,%2,%3};"
        : "+f"(c[0]), "+f"(c[1]), "+f"(c[2]), "+f"(c[3])
        : "r"(a[0]), "r"(a[1]), "r"(a[2]), "r"(a[3]), "r"(b[0]), "r"(b[1]));
}

// ldmatrix x4: 4 8x4-tf32 tiles; thread i supplies row i%8 of tile i/8.
__device__ __forceinline__ void ldsm4(uint32_t* r, const uint32_t* p) {
    uint32_t addr = (uint32_t)__cvta_generic_to_shared(p);
    asm volatile("ldmatrix.sync.aligned.m8n8.x4.shared.b16 {%0,%1,%2,%3}, [%4];"
        : "=r"(r[0]), "=r"(r[1]), "=r"(r[2]), "=r"(r[3]) : "r"(addr));
}

// 16B async copy gmem -> smem
__device__ __forceinline__ void cp16(uint32_t smem_addr, const void* g) {
    asm volatile("cp.async.cg.shared.global [%0], [%1], 16;"
                 :: "r"(smem_addr), "l"(g) : "memory");
}

// float4 load summing the same offset across the 4 ctx partials.
__device__ __forceinline__ float4 ld_sum4(const float* p) {
    float4 v = *(const float4*)p;
    const float* q = p;
#pragma unroll
    for (int s = 1; s < 4; s++) {
        q += CTXSZ;
        float4 w = *(const float4*)q;
        v.x += w.x; v.y += w.y; v.z += w.z; v.w += w.w;
    }
    return v;
}

// ===========================================================================
// Unified tensor-core tf32 GEMM: D[m,n] = sum_k A[m,k]*B[n,k]
//  mode 0/1/2 (z picks Q/K/V): proj; mode 3: out-proj split-K x2 (z=split,
//    A = sum of 4 ctx partials, writes g_out partial `split`, bias on split 0)
//  mode 4: scores; mode 5: attn*V split-K x4 (z = bh*4+split, K=128/split)
// Template MT = M tile (128 or 64). N tile fixed 64. 256 threads.
// Tiles land raw fp32 in smem via cp.async (3 buffers, depth-2, 1 sync/chunk);
// raw fp32 bits feed mma.tf32 directly (HW truncates to tf32's 19 bits).
// ===========================================================================
template<int MT>
__global__ __launch_bounds__(256) void tc_gemm(
    const float* __restrict__ A0, const float* __restrict__ A1, const float* __restrict__ A2,
    const float* __restrict__ B0, const float* __restrict__ B1, const float* __restrict__ B2,
    const float* __restrict__ bias0, const float* __restrict__ bias1, const float* __restrict__ bias2,
    float* __restrict__ attn, int mode, int kTot)
{
    constexpr int WMc = (MT == 128) ? 4 : 2;
    constexpr int WNc = 8 / WMc;
    constexpr int NFR = 64 / (WNc * 8);          // 128:4, 64:2
    constexpr int AL  = MT / 32;
    constexpr int AWp = MT * 36;
    constexpr int BUFWp = (MT + 64) * 36;

    extern __shared__ uint32_t smem_u[];
    int tid = threadIdx.x;
    int wid = tid >> 5, lane = tid & 31;
    int wm = wid % WMc, wn = wid / WMc;
    int g = lane >> 2, t4 = lane & 3;

    // ldmatrix per-thread row offsets (words)
    int mrow = lane & 7, msel = lane >> 3;
    int a_off = ((msel & 1) * 8 + mrow) * 36 + (msel >> 1) * 4;
    int b_off = ((msel >> 1) * 8 + mrow) * 36 + (msel & 1) * 4;

    int row0 = blockIdx.y * MT;
    int n0   = blockIdx.x * 64;
    int bh   = blockIdx.z;

    const float* Ap; const float* Bp; const float* biasp = nullptr;
    int ldA, ldB, emode, split = 0;
    if (mode == 0) {
        int w = bh;
        Ap = (w == 0) ? A0 : (w == 1) ? A1 : A2;
        Bp = (w == 0) ? B0 : (w == 1) ? B1 : B2;
        biasp = (w == 0) ? bias0 : (w == 1) ? bias1 : bias2;
        ldA = Dn; ldB = Dn; emode = w;
    } else if (mode == 3) {
        split = bh;
        Ap = g_ctx + split * 256;                // K offset into ctx columns
        Bp = B0 + split * 256;
        biasp = bias0; ldA = Dn; ldB = Dn; emode = 3;
    } else if (mode == 4) {
        Ap = g_q + (size_t)bh * Sn * DKn;        // M = queries (i)
        Bp = g_k + (size_t)bh * Sn * DKn;        // N = keys (j)
        ldA = DKn; ldB = DKn; emode = 4;
    } else {
        split = bh & 3; bh >>= 2;
        Ap = attn + (size_t)bh * Sn * Sn + split * 128;
        Bp = g_vT + (size_t)bh * DKn * Sn + split * 128;
        ldA = Sn; ldB = Sn; emode = 5;
    }
    Ap += (size_t)row0 * ldA;
    Bp += (size_t)n0 * ldB;
    const bool sumA = (mode == 3);
    const bool doBias = (mode == 0) || (mode == 3 && split == 0);

    uint32_t smem_addr0 = (uint32_t)__cvta_generic_to_shared(smem_u);
    int rr = tid >> 3, c4 = tid & 7;

    // issue one 32-k chunk c into buffer b (one commit group per call)
    auto issue_chunk = [&](int c, int b) {
        int k0 = c * 32;
        uint32_t Ab = smem_addr0 + (uint32_t)(b * BUFWp) * 4u;
        uint32_t Bb = Ab + (uint32_t)AWp * 4u;
        if (sumA) {
            float* As = (float*)(smem_u + b * BUFWp);
#pragma unroll
            for (int l = 0; l < AL; l++) {
                float4 v = ld_sum4(Ap + (size_t)(rr + l * 32) * ldA + k0 + c4 * 4);
                float* d = As + (rr + l * 32) * 36 + c4 * 4;
                d[0] = v.x; d[1] = v.y; d[2] = v.z; d[3] = v.w;
            }
        } else {
#pragma unroll
            for (int l = 0; l < AL; l++)
                cp16(Ab + (uint32_t)((rr + l * 32) * 36 + c4 * 4) * 4u,
                     Ap + (size_t)(rr + l * 32) * ldA + k0 + c4 * 4);
        }
#pragma unroll
        for (int l = 0; l < 2; l++)
            cp16(Bb + (uint32_t)((rr + l * 32) * 36 + c4 * 4) * 4u,
                 Bp + (size_t)(rr + l * 32) * ldB + k0 + c4 * 4);
        asm volatile("cp.async.commit_group;" ::: "memory");
    };

    float acc[2][NFR][4];
#pragma unroll
    for (int mi = 0; mi < 2; mi++)
#pragma unroll
        for (int ni = 0; ni < NFR; ni++)
#pragma unroll
            for (int q = 0; q < 4; q++) acc[mi][ni][q] = 0.f;

    int nk = kTot / 32;
    issue_chunk(0, 0);
    if (nk > 1) issue_chunk(1, 1);

    for (int kc = 0; kc < nk; kc++) {
        if (kc + 1 < nk) asm volatile("cp.async.wait_group 1;" ::: "memory");
        else             asm volatile("cp.async.wait_group 0;" ::: "memory");
        __syncthreads();
        // safe: buffer (kc+2)%3 was last read at iteration kc-1, and every
        // warp passed this iteration's barrier after finishing that MMA.
        if (kc + 2 < nk) issue_chunk(kc + 2, (kc + 2) % 3);

        const uint32_t* As = smem_u + (kc % 3) * BUFWp;
        const uint32_t* Bs = As + AWp;
#pragma unroll
        for (int kk = 0; kk < 4; kk++) {
            uint32_t a[2][4], b[NFR][2];
#pragma unroll
            for (int mi = 0; mi < 2; mi++)
                ldsm4(a[mi], As + (wm * 32 + mi * 16) * 36 + a_off + kk * 8);
#pragma unroll
            for (int np = 0; np < NFR / 2; np++) {
                uint32_t rb[4];
                ldsm4(rb, Bs + (wn * (NFR * 8) + np * 16) * 36 + b_off + kk * 8);
                b[np * 2][0] = rb[0]; b[np * 2][1] = rb[1];
                b[np * 2 + 1][0] = rb[2]; b[np * 2 + 1][1] = rb[3];
            }
            // raw fp32 bits -> mma.tf32 (HW reads top 19 bits; RZ truncation)
#pragma unroll
            for (int mi = 0; mi < 2; mi++)
#pragma unroll
                for (int ni = 0; ni < NFR; ni++)
                    mma_tf32(acc[mi][ni], a[mi], b[ni]);
        }
    }

#pragma unroll
    for (int mi = 0; mi < 2; mi++) {
        int row = row0 + wm * 32 + mi * 16 + g;
#pragma unroll
        for (int ni = 0; ni < NFR; ni++) {
            int col = n0 + wn * (NFR * 8) + ni * 8 + 2 * t4;
            float v0 = acc[mi][ni][0], v1 = acc[mi][ni][1];
            float v2 = acc[mi][ni][2], v3 = acc[mi][ni][3];
            if (doBias) {
                float b0v = biasp[col], b1v = biasp[col + 1];
                v0 += b0v; v1 += b1v; v2 += b0v; v3 += b1v;
            }
            if (emode <= 2) {
                int b = row >> 9, s = row & 511;
                int h = col >> 6, dk = col & 63;
                if (emode == 0) {
                    float* p = g_q + (((size_t)(b * Hn + h)) * Sn + s) * DKn + dk;
                    *(float2*)p = make_float2(v0, v1);
                    *(float2*)(p + 8 * DKn) = make_float2(v2, v3);
                } else if (emode == 1) {
                    float* p = g_k + (((size_t)(b * Hn + h)) * Sn + s) * DKn + dk;
                    *(float2*)p = make_float2(v0, v1);
                    *(float2*)(p + 8 * DKn) = make_float2(v2, v3);
                } else {
                    float* p = g_vT + (((size_t)(b * Hn + h)) * DKn + dk) * Sn + s;
                    p[0] = v0; p[Sn] = v1; p[8] = v2; p[Sn + 8] = v3;
                }
            } else if (emode == 3) {
                float* p = g_out + (size_t)split * CTXSZ + (size_t)row * Dn + col;
                *(float2*)p = make_float2(v0, v1);
                *(float2*)(p + 8 * Dn) = make_float2(v2, v3);
            } else if (emode == 4) {
                float* p = attn + ((size_t)bh * Sn + row) * Sn + col;
                *(float2*)p = make_float2(v0 * 0.125f, v1 * 0.125f);
                *(float2*)(p + 8 * Sn) = make_float2(v2 * 0.125f, v3 * 0.125f);
            } else {
                int b = bh >> 3, h = bh & 7;
                float* p = g_ctx + (size_t)split * CTXSZ
                         + ((size_t)b * Sn + row) * Dn + h * DKn + col;
                *(float2*)p = make_float2(v0, v1);
                *(float2*)(p + 8 * Dn) = make_float2(v2, v3);
            }
        }
    }
}

// ===========================================================================
// Fused relative-position bias + mask + softmax (unchanged from R11).
// ===========================================================================
__global__ __launch_bounds__(256) void bias_softmax_kernel(
    const int* __restrict__ rp, const float* __restrict__ rel_table,
    const int* __restrict__ mask, float* __restrict__ attn)
{
    __shared__ __align__(16) uint32_t qs_p[8 * 68];
    __shared__ __align__(16) uint32_t pool[2 * 64 * 68];   // vbuf, later s_row
    __shared__ float tms[NTAB + 3];
    __shared__ int mask_s[Sn];

    uint32_t* vbuf0 = pool;
    uint32_t* vbuf1 = pool + 64 * 68;
    float* s_row = (float*)pool;                 // aliased after tile loop

    int i = blockIdx.x;
    int b = blockIdx.y;
    int tid = threadIdx.x;
    int wid = tid >> 5, lane = tid & 31;
    int g = lane >> 2, t4 = lane & 3;
    int half = wid >> 2;
    int jq = wid & 3;

    if (tid < NTAB) {
        float s = 0.f;
#pragma unroll
        for (int e = 0; e < DKn; e++) s += rel_table[tid * DKn + e];
        tms[tid] = __uint_as_float(to_tf32(s * (1.0f / DKn)));
    }
    for (int l = tid; l < Hn * DKn; l += 256) {
        int h = l >> 6, d = l & 63;
        qs_p[h * 68 + d] = to_tf32(g_q[(((size_t)b * Hn + h) * Sn + i) * DKn + d]);
    }
    {
        mask_s[tid] = mask[b * Sn + tid];
        mask_s[tid + 256] = mask[b * Sn + tid + 256];
    }

    const int4* src = (const int4*)(rp + (((size_t)b * Sn + i) * Sn) * DKn);

    int4 pre[8];
#pragma unroll
    for (int l = 0; l < 8; l++) pre[l] = src[tid + l * 256];
    __syncthreads();

    float cb[4][4];                              // bias results, all 4 iterations
    for (int jt2 = 0; jt2 < 4; jt2++) {
#pragma unroll
        for (int l = 0; l < 8; l++) {
            uint32_t* vb = (l < 4) ? vbuf0 : vbuf1;
            int q4 = tid + (l & 3) * 256;
            int4 v = pre[l];
            int e = q4 * 4;
            int j = e >> 6, d = e & 63;
            float4 f;
            f.x = tms[min(max(v.x, -16), 16) + 16];
            f.y = tms[min(max(v.y, -16), 16) + 16];
            f.z = tms[min(max(v.z, -16), 16) + 16];
            f.w = tms[min(max(v.w, -16), 16) + 16];
            *(float4*)&vb[j * 68 + d] = f;
        }
        __syncthreads();
        if (jt2 + 1 < 4) {
#pragma unroll
            for (int l = 0; l < 8; l++)
                pre[l] = src[(size_t)(jt2 + 1) * 2048 + tid + l * 256];
        }
        const uint32_t* Vb = half ? vbuf1 : vbuf0;
        float c[4] = {0.f, 0.f, 0.f, 0.f};
#pragma unroll
        for (int kk = 0; kk < 8; kk++) {
            int kb = kk * 8 + t4;
            uint32_t a[4], bb[2];
            int r = (jq * 16 + g) * 68 + kb;
            a[0] = Vb[r];
            a[1] = Vb[r + 8 * 68];
            a[2] = Vb[r + 4];
            a[3] = Vb[r + 8 * 68 + 4];
            bb[0] = qs_p[g * 68 + kb];
            bb[1] = qs_p[g * 68 + kb + 4];
            mma_tf32(c, a, bb);
        }
#pragma unroll
        for (int q = 0; q < 4; q++) cb[jt2][q] = c[q];
        __syncthreads();
    }

    // vbuf dead; write register-held bias into s_row (aliased storage)
#pragma unroll
    for (int jt2 = 0; jt2 < 4; jt2++) {
        int jbase = (jt2 * 2 + half) * 64 + jq * 16;
        s_row[(2 * t4) * Sn + jbase + g] = cb[jt2][0];
        s_row[(2 * t4 + 1) * Sn + jbase + g] = cb[jt2][1];
        s_row[(2 * t4) * Sn + jbase + g + 8] = cb[jt2][2];
        s_row[(2 * t4 + 1) * Sn + jbase + g + 8] = cb[jt2][3];
    }
    __syncthreads();

    float* grow = attn + (((size_t)(b * Hn + wid)) * Sn + i) * Sn;
    float v[16];
    float mx = -3.0e38f;
#pragma unroll
    for (int k = 0; k < 16; k++) {
        int j = lane + k * 32;
        float x = grow[j] + s_row[wid * Sn + j];
        if (mask_s[j] == 0) x = -1e9f;
        v[k] = x;
        mx = fmaxf(mx, x);
    }
#pragma unroll
    for (int off = 16; off; off >>= 1) mx = fmaxf(mx, __shfl_xor_sync(0xffffffffu, mx, off));
    float s = 0.f;
#pragma unroll
    for (int k = 0; k < 16; k++) { v[k] = __expf(v[k] - mx); s += v[k]; }
#pragma unroll
    for (int off = 16; off; off >>= 1) s += __shfl_xor_sync(0xffffffffu, s, off);
    float inv = 1.0f / s;
#pragma unroll
    for (int k = 0; k < 16; k++) grow[lane + k * 32] = v[k] * inv;
}

// ---------------------------------------------------------------------------
// y = LayerNorm(out0 + out1 + query) * gamma + beta
// ---------------------------------------------------------------------------
__global__ __launch_bounds__(256) void ln_kernel(const float* __restrict__ query,
                                                 const float* __restrict__ gamma,
                                                 const float* __restrict__ beta,
                                                 float* __restrict__ y)
{
    int row = blockIdx.x;
    int tid = threadIdx.x;
    size_t base = (size_t)row * Dn;
    float x0 = g_out[base + tid] + g_out[CTXSZ + base + tid] + query[base + tid];
    float x1 = g_out[base + tid + 256] + g_out[CTXSZ + base + tid + 256] + query[base + tid + 256];
    float s = x0 + x1, sq = x0 * x0 + x1 * x1;
    __shared__ float r1[8], r2[8];
#pragma unroll
    for (int off = 16; off; off >>= 1) {
        s += __shfl_xor_sync(0xffffffffu, s, off);
        sq += __shfl_xor_sync(0xffffffffu, sq, off);
    }
    if ((tid & 31) == 0) { r1[tid >> 5] = s; r2[tid >> 5] = sq; }
    __syncthreads();
    s = 0.f; sq = 0.f;
#pragma unroll
    for (int w = 0; w < 8; w++) { s += r1[w]; sq += r2[w]; }
    float mean = s * (1.0f / Dn);
    float var = sq * (1.0f / Dn) - mean * mean;
    float rstd = rsqrtf(var + 1e-5f);
    y[base + tid]       = (x0 - mean) * rstd * gamma[tid] + beta[tid];
    y[base + tid + 256] = (x1 - mean) * rstd * gamma[tid + 256] + beta[tid + 256];
}

// ---------------------------------------------------------------------------
extern "C" void kernel_launch(void* const* d_in, const int* in_sizes, int n_in,
                              void* d_out, int out_size)
{
    (void)in_sizes; (void)n_in; (void)out_size;
    const float* query = (const float*)d_in[0];
    const float* key   = (const float*)d_in[1];
    const float* value = (const float*)d_in[2];
    const float* Wq = (const float*)d_in[3];
    const float* bq = (const float*)d_in[4];
    const float* Wk = (const float*)d_in[5];
    const float* bk = (const float*)d_in[6];
    const float* Wv = (const float*)d_in[7];
    const float* bv = (const float*)d_in[8];
    const float* Wo = (const float*)d_in[9];
    const float* bo = (const float*)d_in[10];
    const float* rel_table = (const float*)d_in[11];
    const float* gamma = (const float*)d_in[12];
    const float* beta  = (const float*)d_in[13];
    const int* mask = (const int*)d_in[14];
    const int* rp   = (const int*)d_in[15];

    float* y = (float*)d_out;                        // [B,S,D]
    float* attn = y + (size_t)Bn * Sn * Dn;          // [B,H,S,S]

    const int SMB128 = 3 * (128 + 64) * 36 * 4;      // 82944
    const int SMB64  = 3 * (64 + 64) * 36 * 4;       // 55296
    cudaFuncSetAttribute(tc_gemm<128>, cudaFuncAttributeMaxDynamicSharedMemorySize, SMB128);
    cudaFuncSetAttribute(tc_gemm<64>,  cudaFuncAttributeMaxDynamicSharedMemorySize, SMB64);

    // fused QKV projections (MT=128, 384 CTAs)
    tc_gemm<128><<<dim3(8, 16, 3), 256, SMB128>>>(query, key, value, Wq, Wk, Wv,
                                                  bq, bk, bv, nullptr, 0, 512);
    // scores
    tc_gemm<128><<<dim3(8, 4, 32), 256, SMB128>>>(nullptr, nullptr, nullptr, nullptr, nullptr, nullptr,
                                                  nullptr, nullptr, nullptr, attn, 4, 64);
    // fused rel-pos bias + mask + softmax (bias via mma, smem-reduced)
    bias_softmax_kernel<<<dim3(Sn, Bn), 256>>>(rp, rel_table, mask, attn);
    // attn @ V  split-K x4 -> 1024 CTAs, each K=128, writes partial ctx buffer
    tc_gemm<64><<<dim3(1, 8, 128), 256, SMB64>>>(nullptr, nullptr, nullptr, nullptr, nullptr, nullptr,
                                                 nullptr, nullptr, nullptr, attn, 5, 128);
    // out projection split-K x2 (A = sum of 4 ctx partials during load)
    tc_gemm<64><<<dim3(8, 32, 2), 256, SMB64>>>(nullptr, nullptr, nullptr, Wo, nullptr, nullptr,
                                                bo, nullptr, nullptr, nullptr, 3, 256);
    ln_kernel<<<Bn * Sn, 256>>>(query, gamma, beta, y);
}

// round 17
// speedup vs baseline: 1.5973x; 1.0251x over previous
#include <cuda_runtime.h>
#include <math.h>
#include <stdint.h>

#define Bn 4
#define Sn 512
#define Dn 512
#define Hn 8
#define DKn 64
#define NTAB 33
#define CTXSZ ((size_t)Bn*Sn*Dn)   // 1048576 floats

// Scratch (no allocations allowed -> __device__ globals)
__device__ float g_q[Bn*Hn*Sn*DKn];
__device__ float g_k[Bn*Hn*Sn*DKn];
__device__ float g_vT[Bn*Hn*DKn*Sn];           // V transposed: [b,h,dk,s]
__device__ float g_ctx[2 * (size_t)Bn*Sn*Dn];  // 2 split-K partials (attn*V)
__device__ float g_out[2 * (size_t)Bn*Sn*Dn];  // 2 split-K partials (out-proj)

__device__ __forceinline__ uint32_t to_tf32(float f) {
    uint32_t u;
    asm("cvt.rna.tf32.f32 %0, %1;" : "=r"(u) : "f"(f));
    return u;
}

__device__ __forceinline__ void mma_tf32(float* c, const uint32_t* a, const uint32_t* b) {
    asm volatile(
        "mma.sync.aligned.m16n8k8.row.col.f32.tf32.tf32.f32 "
        "{%0,%1,%2,%3}, {%4,%5,%6,%7}, {%8,%9}, {%0,%1,%2,%3};"
        : "+f"(c[0]), "+f"(c[1]), "+f"(c[2]), "+f"(c[3])
        : "r"(a[0]), "r"(a[1]), "r"(a[2]), "r"(a[3]), "r"(b[0]), "r"(b[1]));
}

// ldmatrix x4: 4 8x4-tf32 tiles; thread i supplies row i%8 of tile i/8.
__device__ __forceinline__ void ldsm4(uint32_t* r, const uint32_t* p) {
    uint32_t addr = (uint32_t)__cvta_generic_to_shared(p);
    asm volatile("ldmatrix.sync.aligned.m8n8.x4.shared.b16 {%0,%1,%2,%3}, [%4];"
        : "=r"(r[0]), "=r"(r[1]), "=r"(r[2]), "=r"(r[3]) : "r"(addr));
}

// 16B async copy gmem -> smem
__device__ __forceinline__ void cp16(uint32_t smem_addr, const void* g) {
    asm volatile("cp.async.cg.shared.global [%0], [%1], 16;"
                 :: "r"(smem_addr), "l"(g) : "memory");
}

// float4 load summing the same offset across the 2 ctx partials.
__device__ __forceinline__ float4 ld_sum2(const float* p) {
    float4 v = *(const float4*)p;
    float4 w = *(const float4*)(p + CTXSZ);
    v.x += w.x; v.y += w.y; v.z += w.z; v.w += w.w;
    return v;
}

// ===========================================================================
// Unified tensor-core tf32 GEMM: D[m,n] = sum_k A[m,k]*B[n,k]
//  mode 0/1/2 (z picks Q/K/V): proj; mode 3: out-proj split-K x2 (z=split,
//    A = sum of 2 ctx partials, writes g_out partial `split`, bias on split 0)
//  mode 4: scores; mode 5: attn*V split-K x2 (z = bh*2+split, K=256/split)
// Template MT = M tile (128 or 64). N tile fixed 64. 256 threads.
// Tiles land raw fp32 in smem via cp.async (3 buffers, depth-2, 1 sync/chunk);
// raw fp32 bits feed mma.tf32 directly (HW truncates to tf32's 19 bits).
// ===========================================================================
template<int MT>
__global__ __launch_bounds__(256) void tc_gemm(
    const float* __restrict__ A0, const float* __restrict__ A1, const float* __restrict__ A2,
    const float* __restrict__ B0, const float* __restrict__ B1, const float* __restrict__ B2,
    const float* __restrict__ bias0, const float* __restrict__ bias1, const float* __restrict__ bias2,
    float* __restrict__ attn, int mode, int kTot)
{
    constexpr int WMc = (MT == 128) ? 4 : 2;
    constexpr int WNc = 8 / WMc;
    constexpr int NFR = 64 / (WNc * 8);          // 128:4, 64:2
    constexpr int AL  = MT / 32;
    constexpr int AWp = MT * 36;
    constexpr int BUFWp = (MT + 64) * 36;

    extern __shared__ uint32_t smem_u[];
    int tid = threadIdx.x;
    int wid = tid >> 5, lane = tid & 31;
    int wm = wid % WMc, wn = wid / WMc;
    int g = lane >> 2, t4 = lane & 3;

    // ldmatrix per-thread row offsets (words)
    int mrow = lane & 7, msel = lane >> 3;
    int a_off = ((msel & 1) * 8 + mrow) * 36 + (msel >> 1) * 4;
    int b_off = ((msel >> 1) * 8 + mrow) * 36 + (msel & 1) * 4;

    int row0 = blockIdx.y * MT;
    int n0   = blockIdx.x * 64;
    int bh   = blockIdx.z;

    const float* Ap; const float* Bp; const float* biasp = nullptr;
    int ldA, ldB, emode, split = 0;
    if (mode == 0) {
        int w = bh;
        Ap = (w == 0) ? A0 : (w == 1) ? A1 : A2;
        Bp = (w == 0) ? B0 : (w == 1) ? B1 : B2;
        biasp = (w == 0) ? bias0 : (w == 1) ? bias1 : bias2;
        ldA = Dn; ldB = Dn; emode = w;
    } else if (mode == 3) {
        split = bh;
        Ap = g_ctx + split * 256;                // K offset into ctx columns
        Bp = B0 + split * 256;
        biasp = bias0; ldA = Dn; ldB = Dn; emode = 3;
    } else if (mode == 4) {
        Ap = g_q + (size_t)bh * Sn * DKn;        // M = queries (i)
        Bp = g_k + (size_t)bh * Sn * DKn;        // N = keys (j)
        ldA = DKn; ldB = DKn; emode = 4;
    } else {
        split = bh & 1; bh >>= 1;
        Ap = attn + (size_t)bh * Sn * Sn + split * 256;
        Bp = g_vT + (size_t)bh * DKn * Sn + split * 256;
        ldA = Sn; ldB = Sn; emode = 5;
    }
    Ap += (size_t)row0 * ldA;
    Bp += (size_t)n0 * ldB;
    const bool sumA = (mode == 3);
    const bool doBias = (mode == 0) || (mode == 3 && split == 0);

    uint32_t smem_addr0 = (uint32_t)__cvta_generic_to_shared(smem_u);
    int rr = tid >> 3, c4 = tid & 7;

    // issue one 32-k chunk c into buffer b (one commit group per call)
    auto issue_chunk = [&](int c, int b) {
        int k0 = c * 32;
        uint32_t Ab = smem_addr0 + (uint32_t)(b * BUFWp) * 4u;
        uint32_t Bb = Ab + (uint32_t)AWp * 4u;
        if (sumA) {
            float* As = (float*)(smem_u + b * BUFWp);
#pragma unroll
            for (int l = 0; l < AL; l++) {
                float4 v = ld_sum2(Ap + (size_t)(rr + l * 32) * ldA + k0 + c4 * 4);
                float* d = As + (rr + l * 32) * 36 + c4 * 4;
                d[0] = v.x; d[1] = v.y; d[2] = v.z; d[3] = v.w;
            }
        } else {
#pragma unroll
            for (int l = 0; l < AL; l++)
                cp16(Ab + (uint32_t)((rr + l * 32) * 36 + c4 * 4) * 4u,
                     Ap + (size_t)(rr + l * 32) * ldA + k0 + c4 * 4);
        }
#pragma unroll
        for (int l = 0; l < 2; l++)
            cp16(Bb + (uint32_t)((rr + l * 32) * 36 + c4 * 4) * 4u,
                 Bp + (size_t)(rr + l * 32) * ldB + k0 + c4 * 4);
        asm volatile("cp.async.commit_group;" ::: "memory");
    };

    float acc[2][NFR][4];
#pragma unroll
    for (int mi = 0; mi < 2; mi++)
#pragma unroll
        for (int ni = 0; ni < NFR; ni++)
#pragma unroll
            for (int q = 0; q < 4; q++) acc[mi][ni][q] = 0.f;

    int nk = kTot / 32;
    issue_chunk(0, 0);
    if (nk > 1) issue_chunk(1, 1);

    for (int kc = 0; kc < nk; kc++) {
        if (kc + 1 < nk) asm volatile("cp.async.wait_group 1;" ::: "memory");
        else             asm volatile("cp.async.wait_group 0;" ::: "memory");
        __syncthreads();
        // safe: buffer (kc+2)%3 was last read at iteration kc-1, and every
        // warp passed this iteration's barrier after finishing that MMA.
        if (kc + 2 < nk) issue_chunk(kc + 2, (kc + 2) % 3);

        const uint32_t* As = smem_u + (kc % 3) * BUFWp;
        const uint32_t* Bs = As + AWp;
#pragma unroll
        for (int kk = 0; kk < 4; kk++) {
            uint32_t a[2][4], b[NFR][2];
#pragma unroll
            for (int mi = 0; mi < 2; mi++)
                ldsm4(a[mi], As + (wm * 32 + mi * 16) * 36 + a_off + kk * 8);
#pragma unroll
            for (int np = 0; np < NFR / 2; np++) {
                uint32_t rb[4];
                ldsm4(rb, Bs + (wn * (NFR * 8) + np * 16) * 36 + b_off + kk * 8);
                b[np * 2][0] = rb[0]; b[np * 2][1] = rb[1];
                b[np * 2 + 1][0] = rb[2]; b[np * 2 + 1][1] = rb[3];
            }
            // raw fp32 bits -> mma.tf32 (HW reads top 19 bits; RZ truncation)
#pragma unroll
            for (int mi = 0; mi < 2; mi++)
#pragma unroll
                for (int ni = 0; ni < NFR; ni++)
                    mma_tf32(acc[mi][ni], a[mi], b[ni]);
        }
    }

#pragma unroll
    for (int mi = 0; mi < 2; mi++) {
        int row = row0 + wm * 32 + mi * 16 + g;
#pragma unroll
        for (int ni = 0; ni < NFR; ni++) {
            int col = n0 + wn * (NFR * 8) + ni * 8 + 2 * t4;
            float v0 = acc[mi][ni][0], v1 = acc[mi][ni][1];
            float v2 = acc[mi][ni][2], v3 = acc[mi][ni][3];
            if (doBias) {
                float b0v = biasp[col], b1v = biasp[col + 1];
                v0 += b0v; v1 += b1v; v2 += b0v; v3 += b1v;
            }
            if (emode <= 2) {
                int b = row >> 9, s = row & 511;
                int h = col >> 6, dk = col & 63;
                if (emode == 0) {
                    float* p = g_q + (((size_t)(b * Hn + h)) * Sn + s) * DKn + dk;
                    *(float2*)p = make_float2(v0, v1);
                    *(float2*)(p + 8 * DKn) = make_float2(v2, v3);
                } else if (emode == 1) {
                    float* p = g_k + (((size_t)(b * Hn + h)) * Sn + s) * DKn + dk;
                    *(float2*)p = make_float2(v0, v1);
                    *(float2*)(p + 8 * DKn) = make_float2(v2, v3);
                } else {
                    float* p = g_vT + (((size_t)(b * Hn + h)) * DKn + dk) * Sn + s;
                    p[0] = v0; p[Sn] = v1; p[8] = v2; p[Sn + 8] = v3;
                }
            } else if (emode == 3) {
                float* p = g_out + (size_t)split * CTXSZ + (size_t)row * Dn + col;
                *(float2*)p = make_float2(v0, v1);
                *(float2*)(p + 8 * Dn) = make_float2(v2, v3);
            } else if (emode == 4) {
                float* p = attn + ((size_t)bh * Sn + row) * Sn + col;
                *(float2*)p = make_float2(v0 * 0.125f, v1 * 0.125f);
                *(float2*)(p + 8 * Sn) = make_float2(v2 * 0.125f, v3 * 0.125f);
            } else {
                int b = bh >> 3, h = bh & 7;
                float* p = g_ctx + (size_t)split * CTXSZ
                         + ((size_t)b * Sn + row) * Dn + h * DKn + col;
                *(float2*)p = make_float2(v0, v1);
                *(float2*)(p + 8 * Dn) = make_float2(v2, v3);
            }
        }
    }
}

// ===========================================================================
// Fused relative-position bias + mask + softmax (unchanged from R11).
// ===========================================================================
__global__ __launch_bounds__(256) void bias_softmax_kernel(
    const int* __restrict__ rp, const float* __restrict__ rel_table,
    const int* __restrict__ mask, float* __restrict__ attn)
{
    __shared__ __align__(16) uint32_t qs_p[8 * 68];
    __shared__ __align__(16) uint32_t pool[2 * 64 * 68];   // vbuf, later s_row
    __shared__ float tms[NTAB + 3];
    __shared__ int mask_s[Sn];

    uint32_t* vbuf0 = pool;
    uint32_t* vbuf1 = pool + 64 * 68;
    float* s_row = (float*)pool;                 // aliased after tile loop

    int i = blockIdx.x;
    int b = blockIdx.y;
    int tid = threadIdx.x;
    int wid = tid >> 5, lane = tid & 31;
    int g = lane >> 2, t4 = lane & 3;
    int half = wid >> 2;
    int jq = wid & 3;

    if (tid < NTAB) {
        float s = 0.f;
#pragma unroll
        for (int e = 0; e < DKn; e++) s += rel_table[tid * DKn + e];
        tms[tid] = __uint_as_float(to_tf32(s * (1.0f / DKn)));
    }
    for (int l = tid; l < Hn * DKn; l += 256) {
        int h = l >> 6, d = l & 63;
        qs_p[h * 68 + d] = to_tf32(g_q[(((size_t)b * Hn + h) * Sn + i) * DKn + d]);
    }
    {
        mask_s[tid] = mask[b * Sn + tid];
        mask_s[tid + 256] = mask[b * Sn + tid + 256];
    }

    const int4* src = (const int4*)(rp + (((size_t)b * Sn + i) * Sn) * DKn);

    int4 pre[8];
#pragma unroll
    for (int l = 0; l < 8; l++) pre[l] = src[tid + l * 256];
    __syncthreads();

    float cb[4][4];                              // bias results, all 4 iterations
    for (int jt2 = 0; jt2 < 4; jt2++) {
#pragma unroll
        for (int l = 0; l < 8; l++) {
            uint32_t* vb = (l < 4) ? vbuf0 : vbuf1;
            int q4 = tid + (l & 3) * 256;
            int4 v = pre[l];
            int e = q4 * 4;
            int j = e >> 6, d = e & 63;
            float4 f;
            f.x = tms[min(max(v.x, -16), 16) + 16];
            f.y = tms[min(max(v.y, -16), 16) + 16];
            f.z = tms[min(max(v.z, -16), 16) + 16];
            f.w = tms[min(max(v.w, -16), 16) + 16];
            *(float4*)&vb[j * 68 + d] = f;
        }
        __syncthreads();
        if (jt2 + 1 < 4) {
#pragma unroll
            for (int l = 0; l < 8; l++)
                pre[l] = src[(size_t)(jt2 + 1) * 2048 + tid + l * 256];
        }
        const uint32_t* Vb = half ? vbuf1 : vbuf0;
        float c[4] = {0.f, 0.f, 0.f, 0.f};
#pragma unroll
        for (int kk = 0; kk < 8; kk++) {
            int kb = kk * 8 + t4;
            uint32_t a[4], bb[2];
            int r = (jq * 16 + g) * 68 + kb;
            a[0] = Vb[r];
            a[1] = Vb[r + 8 * 68];
            a[2] = Vb[r + 4];
            a[3] = Vb[r + 8 * 68 + 4];
            bb[0] = qs_p[g * 68 + kb];
            bb[1] = qs_p[g * 68 + kb + 4];
            mma_tf32(c, a, bb);
        }
#pragma unroll
        for (int q = 0; q < 4; q++) cb[jt2][q] = c[q];
        __syncthreads();
    }

    // vbuf dead; write register-held bias into s_row (aliased storage)
#pragma unroll
    for (int jt2 = 0; jt2 < 4; jt2++) {
        int jbase = (jt2 * 2 + half) * 64 + jq * 16;
        s_row[(2 * t4) * Sn + jbase + g] = cb[jt2][0];
        s_row[(2 * t4 + 1) * Sn + jbase + g] = cb[jt2][1];
        s_row[(2 * t4) * Sn + jbase + g + 8] = cb[jt2][2];
        s_row[(2 * t4 + 1) * Sn + jbase + g + 8] = cb[jt2][3];
    }
    __syncthreads();

    float* grow = attn + (((size_t)(b * Hn + wid)) * Sn + i) * Sn;
    float v[16];
    float mx = -3.0e38f;
#pragma unroll
    for (int k = 0; k < 16; k++) {
        int j = lane + k * 32;
        float x = grow[j] + s_row[wid * Sn + j];
        if (mask_s[j] == 0) x = -1e9f;
        v[k] = x;
        mx = fmaxf(mx, x);
    }
#pragma unroll
    for (int off = 16; off; off >>= 1) mx = fmaxf(mx, __shfl_xor_sync(0xffffffffu, mx, off));
    float s = 0.f;
#pragma unroll
    for (int k = 0; k < 16; k++) { v[k] = __expf(v[k] - mx); s += v[k]; }
#pragma unroll
    for (int off = 16; off; off >>= 1) s += __shfl_xor_sync(0xffffffffu, s, off);
    float inv = 1.0f / s;
#pragma unroll
    for (int k = 0; k < 16; k++) grow[lane + k * 32] = v[k] * inv;
}

// ---------------------------------------------------------------------------
// y = LayerNorm(out0 + out1 + query) * gamma + beta
// ---------------------------------------------------------------------------
__global__ __launch_bounds__(256) void ln_kernel(const float* __restrict__ query,
                                                 const float* __restrict__ gamma,
                                                 const float* __restrict__ beta,
                                                 float* __restrict__ y)
{
    int row = blockIdx.x;
    int tid = threadIdx.x;
    size_t base = (size_t)row * Dn;
    float x0 = g_out[base + tid] + g_out[CTXSZ + base + tid] + query[base + tid];
    float x1 = g_out[base + tid + 256] + g_out[CTXSZ + base + tid + 256] + query[base + tid + 256];
    float s = x0 + x1, sq = x0 * x0 + x1 * x1;
    __shared__ float r1[8], r2[8];
#pragma unroll
    for (int off = 16; off; off >>= 1) {
        s += __shfl_xor_sync(0xffffffffu, s, off);
        sq += __shfl_xor_sync(0xffffffffu, sq, off);
    }
    if ((tid & 31) == 0) { r1[tid >> 5] = s; r2[tid >> 5] = sq; }
    __syncthreads();
    s = 0.f; sq = 0.f;
#pragma unroll
    for (int w = 0; w < 8; w++) { s += r1[w]; sq += r2[w]; }
    float mean = s * (1.0f / Dn);
    float var = sq * (1.0f / Dn) - mean * mean;
    float rstd = rsqrtf(var + 1e-5f);
    y[base + tid]       = (x0 - mean) * rstd * gamma[tid] + beta[tid];
    y[base + tid + 256] = (x1 - mean) * rstd * gamma[tid + 256] + beta[tid + 256];
}

// ---------------------------------------------------------------------------
extern "C" void kernel_launch(void* const* d_in, const int* in_sizes, int n_in,
                              void* d_out, int out_size)
{
    (void)in_sizes; (void)n_in; (void)out_size;
    const float* query = (const float*)d_in[0];
    const float* key   = (const float*)d_in[1];
    const float* value = (const float*)d_in[2];
    const float* Wq = (const float*)d_in[3];
    const float* bq = (const float*)d_in[4];
    const float* Wk = (const float*)d_in[5];
    const float* bk = (const float*)d_in[6];
    const float* Wv = (const float*)d_in[7];
    const float* bv = (const float*)d_in[8];
    const float* Wo = (const float*)d_in[9];
    const float* bo = (const float*)d_in[10];
    const float* rel_table = (const float*)d_in[11];
    const float* gamma = (const float*)d_in[12];
    const float* beta  = (const float*)d_in[13];
    const int* mask = (const int*)d_in[14];
    const int* rp   = (const int*)d_in[15];

    float* y = (float*)d_out;                        // [B,S,D]
    float* attn = y + (size_t)Bn * Sn * Dn;          // [B,H,S,S]

    const int SMB128 = 3 * (128 + 64) * 36 * 4;      // 82944
    const int SMB64  = 3 * (64 + 64) * 36 * 4;       // 55296
    cudaFuncSetAttribute(tc_gemm<128>, cudaFuncAttributeMaxDynamicSharedMemorySize, SMB128);
    cudaFuncSetAttribute(tc_gemm<64>,  cudaFuncAttributeMaxDynamicSharedMemorySize, SMB64);

    // fused QKV projections (MT=128, 384 CTAs)
    tc_gemm<128><<<dim3(8, 16, 3), 256, SMB128>>>(query, key, value, Wq, Wk, Wv,
                                                  bq, bk, bv, nullptr, 0, 512);
    // scores
    tc_gemm<128><<<dim3(8, 4, 32), 256, SMB128>>>(nullptr, nullptr, nullptr, nullptr, nullptr, nullptr,
                                                  nullptr, nullptr, nullptr, attn, 4, 64);
    // fused rel-pos bias + mask + softmax (bias via mma, smem-reduced)
    bias_softmax_kernel<<<dim3(Sn, Bn), 256>>>(rp, rel_table, mask, attn);
    // attn @ V  split-K x2 -> 512 CTAs, each K=256, writes partial ctx buffer
    tc_gemm<64><<<dim3(1, 8, 64), 256, SMB64>>>(nullptr, nullptr, nullptr, nullptr, nullptr, nullptr,
                                                nullptr, nullptr, nullptr, attn, 5, 256);
    // out projection split-K x2 (A = sum of 2 ctx partials during load)
    tc_gemm<64><<<dim3(8, 32, 2), 256, SMB64>>>(nullptr, nullptr, nullptr, Wo, nullptr, nullptr,
                                                bo, nullptr, nullptr, nullptr, 3, 256);
    ln_kernel<<<Bn * Sn, 256>>>(query, gamma, beta, y);
}